// round 6
// baseline (speedup 1.0000x reference)
#include <cuda_runtime.h>
#include <cuda_bf16.h>

// out = ((x .* s2) H .* g_tilde) H .* s1  per row, H = Sylvester Hadamard 4096.
// One CTA per row, 256 threads, 16 elems/thread held as 4 float4 quads.
// All GMEM + SMEM traffic is 128-bit (LDG.128/STG.128/LDS.128/STS.128).
//
// Layout V (elem i = k*1024 + t*4 + j):
//   in-thread bits {0,1}(j) {10,11}(k); lane bits {2..6}; warp bits {7,8,9}
// Layout W (float4 idx = (l&15) + (w&1)*16 + k*32 + (l>>4)*128 + (w>>1)*256):
//   in-thread bits {0,1}(j) {7,8}(k); lane bits {2,3,4,5,9}; warp bits {6,10,11}
// FWHT1: V reg{0,1,10,11} + shfl{2..6}  ->[T V->W]->  W reg{7,8} + shfl{9}
// FWHT2: W reg{0,1,7,8} + shfl{2,3,4,5,9}  ->[T W->V]->  V shfl{6} + reg{10,11}
// Both transposes: every 16-lane LDS/STS phase hits one contiguous 256B block
// -> conflict-free, no skew.

#define DD 4096
#define NTHREADS 256

__device__ float g_tilde_buf[DD];

__global__ void prep_kernel(const float* __restrict__ g_mu,
                            const float* __restrict__ g_rho,
                            const float* __restrict__ eps) {
    int i = blockIdx.x * blockDim.x + threadIdx.x;
    if (i < DD) {
        float r  = g_rho[i];
        float sp = fmaxf(r, 0.0f) + log1pf(expf(-fabsf(r)));   // stable softplus
        g_tilde_buf[i] = g_mu[i] + sp * eps[i];
    }
}

// ---- butterflies on element bit 0 / bit 1 inside one float4 ----
__device__ __forceinline__ void bstage_j0(float4& q) {
    float a = q.x, b = q.y, c = q.z, d = q.w;
    q.x = a + b; q.y = a - b; q.z = c + d; q.w = c - d;
}
__device__ __forceinline__ void bstage_j1(float4& q) {
    float a = q.x, b = q.y, c = q.z, d = q.w;
    q.x = a + c; q.y = b + d; q.z = a - c; q.w = b - d;
}

// ---- butterfly across register quads (quad-index bit selected by MASK) ----
template <int MASK>
__device__ __forceinline__ void quad_stage(float4 v[4]) {
#pragma unroll
    for (int k = 0; k < 4; k++) {
        if (!(k & MASK)) {
            float4 a = v[k], b = v[k | MASK];
            v[k].x        = a.x + b.x; v[k].y        = a.y + b.y;
            v[k].z        = a.z + b.z; v[k].w        = a.w + b.w;
            v[k | MASK].x = a.x - b.x; v[k | MASK].y = a.y - b.y;
            v[k | MASK].z = a.z - b.z; v[k | MASK].w = a.w - b.w;
        }
    }
}

// ---- butterfly across lanes (lower lane -> a+b, upper -> a-b) ----
template <int MASK>
__device__ __forceinline__ void shfl_stage4(float4 v[4], int lane) {
    float sgn = (lane & MASK) ? -1.0f : 1.0f;
#pragma unroll
    for (int k = 0; k < 4; k++) {
        float px = __shfl_xor_sync(0xffffffffu, v[k].x, MASK);
        float py = __shfl_xor_sync(0xffffffffu, v[k].y, MASK);
        float pz = __shfl_xor_sync(0xffffffffu, v[k].z, MASK);
        float pw = __shfl_xor_sync(0xffffffffu, v[k].w, MASK);
        v[k].x = fmaf(sgn, v[k].x, px);
        v[k].y = fmaf(sgn, v[k].y, py);
        v[k].z = fmaf(sgn, v[k].z, pz);
        v[k].w = fmaf(sgn, v[k].w, pw);
    }
}

__device__ __forceinline__ float4 mul4(float4 a, float4 b) {
    float4 r; r.x = a.x*b.x; r.y = a.y*b.y; r.z = a.z*b.z; r.w = a.w*b.w;
    return r;
}

__global__ __launch_bounds__(NTHREADS)
void whvi_kernel(const float* __restrict__ x,
                 const float* __restrict__ s1,
                 const float* __restrict__ s2,
                 float* __restrict__ out) {
    __shared__ float4 sm4[DD / 4];   // 16 KB

    const int t = threadIdx.x;
    const int l = t & 31;
    const int w = t >> 5;
    const long row = blockIdx.x;

    const float4* __restrict__ x4  = reinterpret_cast<const float4*>(x + row * (long)DD);
    const float4* __restrict__ s24 = reinterpret_cast<const float4*>(s2);
    const float4* __restrict__ s14 = reinterpret_cast<const float4*>(s1);
    const float4* __restrict__ gt4 = reinterpret_cast<const float4*>(g_tilde_buf);
    float4* __restrict__ out4 = reinterpret_cast<float4*>(out + row * (long)DD);

    float4 v[4];

    // ---- load row (layout V, 512B/warp/quad, coalesced), scale by s2 ----
#pragma unroll
    for (int k = 0; k < 4; k++)
        v[k] = mul4(__ldcs(x4 + k * 256 + t), __ldg(s24 + k * 256 + t));

    // ---- FWHT #1 in V: bits {0,1} (intra-quad), {10,11} (quads), {2..6} (shfl) ----
#pragma unroll
    for (int k = 0; k < 4; k++) { bstage_j0(v[k]); bstage_j1(v[k]); }
    quad_stage<1>(v); quad_stage<2>(v);
    shfl_stage4<1>(v, l); shfl_stage4<2>(v, l); shfl_stage4<4>(v, l);
    shfl_stage4<8>(v, l); shfl_stage4<16>(v, l);

    // ---- transpose V -> W ----
#pragma unroll
    for (int k = 0; k < 4; k++)
        sm4[k * 256 + t] = v[k];
    __syncthreads();

    const int rw = (l & 15) + (w & 1) * 16 + (l >> 4) * 128 + (w >> 1) * 256;
    float4 gt[4];
#pragma unroll
    for (int k = 0; k < 4; k++) {
        v[k]  = sm4[rw + k * 32];
        gt[k] = __ldg(gt4 + rw + k * 32);   // prefetch, overlaps next stages
    }

    // ---- FWHT #1 in W: bits {7,8} (quads), {9} (shfl) -> FWHT #1 complete ----
    quad_stage<1>(v); quad_stage<2>(v);
    shfl_stage4<16>(v, l);

    // ---- elementwise g_tilde (layout W) ----
#pragma unroll
    for (int k = 0; k < 4; k++)
        v[k] = mul4(v[k], gt[k]);

    // ---- FWHT #2 in W: bits {0,1}, {7,8}, {2,3,4,5,9} ----
#pragma unroll
    for (int k = 0; k < 4; k++) { bstage_j0(v[k]); bstage_j1(v[k]); }
    quad_stage<1>(v); quad_stage<2>(v);
    shfl_stage4<1>(v, l); shfl_stage4<2>(v, l); shfl_stage4<4>(v, l);
    shfl_stage4<8>(v, l); shfl_stage4<16>(v, l);

    // ---- transpose W -> V ----
    __syncthreads();   // all reads of previous transpose done
#pragma unroll
    for (int k = 0; k < 4; k++)
        sm4[rw + k * 32] = v[k];
    __syncthreads();

    float4 s1f[4];
#pragma unroll
    for (int k = 0; k < 4; k++) {
        v[k]   = sm4[k * 256 + t];
        s1f[k] = __ldg(s14 + k * 256 + t);   // prefetch, overlaps next stages
    }

    // ---- FWHT #2 in V: bit {6} (shfl), bits {10,11} (quads) -> complete ----
    shfl_stage4<16>(v, l);
    quad_stage<1>(v); quad_stage<2>(v);

    // ---- scale by s1, store (layout V, coalesced, streaming) ----
#pragma unroll
    for (int k = 0; k < 4; k++)
        __stcs(out4 + k * 256 + t, mul4(v[k], s1f[k]));
}

extern "C" void kernel_launch(void* const* d_in, const int* in_sizes, int n_in,
                              void* d_out, int out_size) {
    const float* x     = (const float*)d_in[0];
    const float* s1    = (const float*)d_in[1];
    const float* s2    = (const float*)d_in[2];
    const float* g_mu  = (const float*)d_in[3];
    const float* g_rho = (const float*)d_in[4];
    const float* eps   = (const float*)d_in[5];
    float* out = (float*)d_out;

    int B = in_sizes[0] / DD;   // 4096

    prep_kernel<<<DD / NTHREADS, NTHREADS>>>(g_mu, g_rho, eps);
    whvi_kernel<<<B, NTHREADS>>>(x, s1, s2, out);
}

// round 13
// speedup vs baseline: 1.1487x; 1.1487x over previous
#include <cuda_runtime.h>
#include <cuda_bf16.h>

// out = ((x .* s2) H .* g_tilde) H .* s1  per row, H = Sylvester Hadamard 4096.
// One CTA per row, 128 threads, 32 elems/thread as 8 float4 quads.
// All GMEM + SMEM traffic 128-bit; only 8 shuffle stages total.
//
// Layout V (elem i = k*512 + t*4 + j, t in [0,128), k in [0,8)):
//   bits: j{0,1}, lane{2..6}, warp{7,8}, k{9,10,11};  f4 idx = k*128 + t
// Layout W (f4 idx = (l&15) + k*16 + (l>>4)*128 + w*256):
//   bits: j{0,1}, lane&15 {2..5}, k{6,7,8}, lane bit4 {9}, warp{10,11}
// FWHT1: V j{0,1} + quad{9,10,11} + shfl{2..5}  ->[T]->  W quad{6,7,8}
// FWHT2: W j{0,1} + quad{6,7,8} + shfl{2..5}    ->[T]->  V quad{9,10,11}
// Each 8-lane LDS/STS phase touches one contiguous 128B block: conflict-free.

#define DD 4096
#define NTHREADS 128

__device__ float g_tilde_buf[DD];

__global__ void prep_kernel(const float* __restrict__ g_mu,
                            const float* __restrict__ g_rho,
                            const float* __restrict__ eps) {
    int i = blockIdx.x * blockDim.x + threadIdx.x;
    if (i < DD) {
        float r  = g_rho[i];
        float sp = fmaxf(r, 0.0f) + log1pf(expf(-fabsf(r)));   // stable softplus
        g_tilde_buf[i] = g_mu[i] + sp * eps[i];
    }
}

// ---- butterflies on element bit 0 / bit 1 inside one float4 ----
__device__ __forceinline__ void bstage_j0(float4& q) {
    float a = q.x, b = q.y, c = q.z, d = q.w;
    q.x = a + b; q.y = a - b; q.z = c + d; q.w = c - d;
}
__device__ __forceinline__ void bstage_j1(float4& q) {
    float a = q.x, b = q.y, c = q.z, d = q.w;
    q.x = a + c; q.y = b + d; q.z = a - c; q.w = b - d;
}

// ---- butterfly across the 8 register quads (quad-index bit = MASK) ----
template <int MASK>
__device__ __forceinline__ void quad_stage(float4 v[8]) {
#pragma unroll
    for (int k = 0; k < 8; k++) {
        if (!(k & MASK)) {
            float4 a = v[k], b = v[k | MASK];
            v[k].x        = a.x + b.x; v[k].y        = a.y + b.y;
            v[k].z        = a.z + b.z; v[k].w        = a.w + b.w;
            v[k | MASK].x = a.x - b.x; v[k | MASK].y = a.y - b.y;
            v[k | MASK].z = a.z - b.z; v[k | MASK].w = a.w - b.w;
        }
    }
}

// ---- butterfly across lanes (lower -> a+b, upper -> a-b) ----
template <int MASK>
__device__ __forceinline__ void shfl_stage(float4 v[8], int lane) {
    float sgn = (lane & MASK) ? -1.0f : 1.0f;
#pragma unroll
    for (int k = 0; k < 8; k++) {
        float px = __shfl_xor_sync(0xffffffffu, v[k].x, MASK);
        float py = __shfl_xor_sync(0xffffffffu, v[k].y, MASK);
        float pz = __shfl_xor_sync(0xffffffffu, v[k].z, MASK);
        float pw = __shfl_xor_sync(0xffffffffu, v[k].w, MASK);
        v[k].x = fmaf(sgn, v[k].x, px);
        v[k].y = fmaf(sgn, v[k].y, py);
        v[k].z = fmaf(sgn, v[k].z, pz);
        v[k].w = fmaf(sgn, v[k].w, pw);
    }
}

__device__ __forceinline__ float4 mul4(float4 a, float4 b) {
    float4 r; r.x = a.x*b.x; r.y = a.y*b.y; r.z = a.z*b.z; r.w = a.w*b.w;
    return r;
}

__global__ __launch_bounds__(NTHREADS)
void whvi_kernel(const float* __restrict__ x,
                 const float* __restrict__ s1,
                 const float* __restrict__ s2,
                 float* __restrict__ out) {
    __shared__ float4 sm4[DD / 4];   // 16 KB

    const int t = threadIdx.x;
    const int l = t & 31;
    const int w = t >> 5;
    const long row = blockIdx.x;

    const float4* __restrict__ x4  = reinterpret_cast<const float4*>(x + row * (long)DD);
    const float4* __restrict__ s24 = reinterpret_cast<const float4*>(s2);
    const float4* __restrict__ s14 = reinterpret_cast<const float4*>(s1);
    const float4* __restrict__ gt4 = reinterpret_cast<const float4*>(g_tilde_buf);
    float4* __restrict__ out4 = reinterpret_cast<float4*>(out + row * (long)DD);

    float4 v[8];

    // ---- load row (layout V, coalesced), scale by s2 ----
#pragma unroll
    for (int k = 0; k < 8; k++)
        v[k] = mul4(__ldcs(x4 + k * 128 + t), __ldg(s24 + k * 128 + t));

    // ---- FWHT #1 in V: bits {0,1}, {9,10,11}, shfl {2..5} ----
#pragma unroll
    for (int k = 0; k < 8; k++) { bstage_j0(v[k]); bstage_j1(v[k]); }
    quad_stage<1>(v); quad_stage<2>(v); quad_stage<4>(v);
    shfl_stage<1>(v, l); shfl_stage<2>(v, l);
    shfl_stage<4>(v, l); shfl_stage<8>(v, l);

    // ---- transpose V -> W ----
#pragma unroll
    for (int k = 0; k < 8; k++)
        sm4[k * 128 + t] = v[k];
    __syncthreads();

    const int rw = (l & 15) + (l >> 4) * 128 + w * 256;
    float4 gt[8];
#pragma unroll
    for (int k = 0; k < 8; k++) {
        v[k]  = sm4[rw + k * 16];
        gt[k] = __ldg(gt4 + rw + k * 16);   // prefetch: overlaps quad stages
    }

    // ---- FWHT #1 in W: bits {6,7,8} (quads) -> FWHT #1 complete ----
    quad_stage<1>(v); quad_stage<2>(v); quad_stage<4>(v);

    // ---- elementwise g_tilde (layout W, coalesced) ----
#pragma unroll
    for (int k = 0; k < 8; k++)
        v[k] = mul4(v[k], gt[k]);

    // ---- FWHT #2 in W: bits {0,1}, {6,7,8}, shfl {2..5} ----
#pragma unroll
    for (int k = 0; k < 8; k++) { bstage_j0(v[k]); bstage_j1(v[k]); }
    quad_stage<1>(v); quad_stage<2>(v); quad_stage<4>(v);
    shfl_stage<1>(v, l); shfl_stage<2>(v, l);
    shfl_stage<4>(v, l); shfl_stage<8>(v, l);

    // ---- transpose W -> V ----
    __syncthreads();   // previous transpose reads done
#pragma unroll
    for (int k = 0; k < 8; k++)
        sm4[rw + k * 16] = v[k];
    __syncthreads();

    float4 s1f[8];
#pragma unroll
    for (int k = 0; k < 8; k++) {
        v[k]   = sm4[k * 128 + t];
        s1f[k] = __ldg(s14 + k * 128 + t);   // prefetch: overlaps quad stages
    }

    // ---- FWHT #2 in V: bits {9,10,11} (quads) -> complete ----
    quad_stage<1>(v); quad_stage<2>(v); quad_stage<4>(v);

    // ---- scale by s1, store (layout V, coalesced, streaming) ----
#pragma unroll
    for (int k = 0; k < 8; k++)
        __stcs(out4 + k * 128 + t, mul4(v[k], s1f[k]));
}

extern "C" void kernel_launch(void* const* d_in, const int* in_sizes, int n_in,
                              void* d_out, int out_size) {
    const float* x     = (const float*)d_in[0];
    const float* s1    = (const float*)d_in[1];
    const float* s2    = (const float*)d_in[2];
    const float* g_mu  = (const float*)d_in[3];
    const float* g_rho = (const float*)d_in[4];
    const float* eps   = (const float*)d_in[5];
    float* out = (float*)d_out;

    int B = in_sizes[0] / DD;   // 4096

    prep_kernel<<<DD / 128, 128>>>(g_mu, g_rho, eps);
    whvi_kernel<<<B, NTHREADS>>>(x, s1, s2, out);
}

// round 16
// speedup vs baseline: 1.2299x; 1.0707x over previous
#include <cuda_runtime.h>
#include <cuda_bf16.h>

// out = ((x .* s2) H .* g_tilde) H .* s1, H = Sylvester Hadamard 4096, per row.
// One CTA per row, 64 threads, 64 elems/thread as 16 float4 quads.
// Only 4 shuffle stages; 2 skewed-SMEM transposes; all GMEM/SMEM 128-bit.
//
// Layout V: f4 = k*64 + t          -> j{0,1} lane{2..6} warp{7} k{8..11}
// Layout W: f4 = (l&3)+k*4+((l>>2)&7)*64+w*512
//                                  -> j{0,1} l&3{2,3} k{4..7} l>>2{8..10} w{11}
// FWHT1: V[j{0,1} + quad{8..11} + shfl{2,3}] -T-> W[quad{4..7}]
// FWHT2: W[j{0,1} + quad{4..7} + shfl{2,3}] -T-> V[quad{8..11}]
// SMEM skew phys = idx + (idx>>6)*4: all four access patterns conflict-free.
// g_tilde is PRE-PERMUTED by prep into W-gather order so its read is coalesced.

#define DD 4096
#define NT 64
#define NQ 16

__device__ float g_tilde_perm[DD];

// g_tilde_perm[p*4+j] = softplus-composed g_tilde at source element src_f4(p)*4+j,
// where p = k*64 + w*32 + l and src_f4 = (l&3) + k*4 + ((l>>2)&7)*64 + w*512.
__global__ void prep_kernel(const float* __restrict__ g_mu,
                            const float* __restrict__ g_rho,
                            const float* __restrict__ eps) {
    int e = blockIdx.x * blockDim.x + threadIdx.x;   // [0, DD)
    if (e < DD) {
        int p = e >> 2, j = e & 3;
        int k = p >> 6, t = p & 63, w = t >> 5, l = t & 31;
        int src = ((l & 3) + k * 4 + ((l >> 2) & 7) * 64 + w * 512) * 4 + j;
        float r  = g_rho[src];
        float sp = fmaxf(r, 0.0f) + log1pf(expf(-fabsf(r)));   // stable softplus
        g_tilde_perm[e] = g_mu[src] + sp * eps[src];
    }
}

// ---- butterflies on element bit 0 / bit 1 inside one float4 ----
__device__ __forceinline__ void bstage_j0(float4& q) {
    float a = q.x, b = q.y, c = q.z, d = q.w;
    q.x = a + b; q.y = a - b; q.z = c + d; q.w = c - d;
}
__device__ __forceinline__ void bstage_j1(float4& q) {
    float a = q.x, b = q.y, c = q.z, d = q.w;
    q.x = a + c; q.y = b + d; q.z = a - c; q.w = b - d;
}

// ---- butterfly across the 16 register quads (quad-index bit = MASK) ----
template <int MASK>
__device__ __forceinline__ void quad_stage(float4 v[NQ]) {
#pragma unroll
    for (int k = 0; k < NQ; k++) {
        if (!(k & MASK)) {
            float4 a = v[k], b = v[k | MASK];
            v[k].x        = a.x + b.x; v[k].y        = a.y + b.y;
            v[k].z        = a.z + b.z; v[k].w        = a.w + b.w;
            v[k | MASK].x = a.x - b.x; v[k | MASK].y = a.y - b.y;
            v[k | MASK].z = a.z - b.z; v[k | MASK].w = a.w - b.w;
        }
    }
}

// ---- butterfly across lanes (lower -> a+b, upper -> a-b) ----
template <int MASK>
__device__ __forceinline__ void shfl_stage(float4 v[NQ], int lane) {
    float sgn = (lane & MASK) ? -1.0f : 1.0f;
#pragma unroll
    for (int k = 0; k < NQ; k++) {
        float px = __shfl_xor_sync(0xffffffffu, v[k].x, MASK);
        float py = __shfl_xor_sync(0xffffffffu, v[k].y, MASK);
        float pz = __shfl_xor_sync(0xffffffffu, v[k].z, MASK);
        float pw = __shfl_xor_sync(0xffffffffu, v[k].w, MASK);
        v[k].x = fmaf(sgn, v[k].x, px);
        v[k].y = fmaf(sgn, v[k].y, py);
        v[k].z = fmaf(sgn, v[k].z, pz);
        v[k].w = fmaf(sgn, v[k].w, pw);
    }
}

__device__ __forceinline__ float4 mul4(float4 a, float4 b) {
    float4 r; r.x = a.x*b.x; r.y = a.y*b.y; r.z = a.z*b.z; r.w = a.w*b.w;
    return r;
}

__global__ __launch_bounds__(NT)
void whvi_kernel(const float* __restrict__ x,
                 const float* __restrict__ s1,
                 const float* __restrict__ s2,
                 float* __restrict__ out) {
    __shared__ float4 sm4[1088];   // 1024 f4 + skew (idx>>6)*4

    const int t = threadIdx.x;
    const int l = t & 31;
    const int w = t >> 5;
    const long row = blockIdx.x;

    const float4* __restrict__ x4  = reinterpret_cast<const float4*>(x + row * (long)DD);
    const float4* __restrict__ s24 = reinterpret_cast<const float4*>(s2);
    const float4* __restrict__ s14 = reinterpret_cast<const float4*>(s1);
    const float4* __restrict__ gt4 = reinterpret_cast<const float4*>(g_tilde_perm);
    float4* __restrict__ out4 = reinterpret_cast<float4*>(out + row * (long)DD);

    float4 v[NQ];

    // ---- load row (layout V, coalesced), scale by s2 ----
#pragma unroll
    for (int k = 0; k < NQ; k++)
        v[k] = mul4(__ldcs(x4 + k * 64 + t), __ldg(s24 + k * 64 + t));

    // ---- FWHT #1 in V: bits {0,1}, quads {8..11}, shfl {2,3} ----
#pragma unroll
    for (int k = 0; k < NQ; k++) { bstage_j0(v[k]); bstage_j1(v[k]); }
    quad_stage<1>(v); quad_stage<2>(v); quad_stage<4>(v); quad_stage<8>(v);
    shfl_stage<1>(v, l); shfl_stage<2>(v, l);

    // ---- transpose V -> W (skewed, conflict-free) ----
#pragma unroll
    for (int k = 0; k < NQ; k++)
        sm4[k * 68 + t] = v[k];                 // phys(k*64+t) = k*68+t
    __syncthreads();
    const int rwp = (l & 3) + ((l >> 2) & 7) * 68 + w * 544;   // phys of W base
#pragma unroll
    for (int k = 0; k < NQ; k++)
        v[k] = sm4[rwp + k * 4];

    // ---- FWHT #1 in W: quads {4..7} -> FWHT #1 complete ----
    quad_stage<1>(v); quad_stage<2>(v); quad_stage<4>(v); quad_stage<8>(v);

    // ---- elementwise g_tilde (pre-permuted -> coalesced) ----
#pragma unroll
    for (int k = 0; k < NQ; k++)
        v[k] = mul4(v[k], __ldg(gt4 + k * 64 + t));

    // ---- FWHT #2 in W: bits {0,1}, quads {4..7}, shfl {2,3} ----
#pragma unroll
    for (int k = 0; k < NQ; k++) { bstage_j0(v[k]); bstage_j1(v[k]); }
    quad_stage<1>(v); quad_stage<2>(v); quad_stage<4>(v); quad_stage<8>(v);
    shfl_stage<1>(v, l); shfl_stage<2>(v, l);

    // ---- transpose W -> V ----
    __syncthreads();   // previous transpose reads done
#pragma unroll
    for (int k = 0; k < NQ; k++)
        sm4[rwp + k * 4] = v[k];
    __syncthreads();
#pragma unroll
    for (int k = 0; k < NQ; k++)
        v[k] = sm4[k * 68 + t];

    // ---- FWHT #2 in V: quads {8..11} -> complete ----
    quad_stage<1>(v); quad_stage<2>(v); quad_stage<4>(v); quad_stage<8>(v);

    // ---- scale by s1, store (layout V, coalesced, streaming) ----
#pragma unroll
    for (int k = 0; k < NQ; k++)
        __stcs(out4 + k * 64 + t, mul4(v[k], __ldg(s14 + k * 64 + t)));
}

extern "C" void kernel_launch(void* const* d_in, const int* in_sizes, int n_in,
                              void* d_out, int out_size) {
    const float* x     = (const float*)d_in[0];
    const float* s1    = (const float*)d_in[1];
    const float* s2    = (const float*)d_in[2];
    const float* g_mu  = (const float*)d_in[3];
    const float* g_rho = (const float*)d_in[4];
    const float* eps   = (const float*)d_in[5];
    float* out = (float*)d_out;

    int B = in_sizes[0] / DD;   // 4096

    prep_kernel<<<DD / 128, 128>>>(g_mu, g_rho, eps);
    whvi_kernel<<<B, NT>>>(x, s1, s2, out);
}